// round 11
// baseline (speedup 1.0000x reference)
#include <cuda_runtime.h>
#include <cuda_bf16.h>
#include <cstdint>
#include <math.h>

#define S      512
#define BATCH  64
#define TLEN   1024
#define OBS_N  32000
#define NTHREADS 512
#define JH     256              // j-columns per CTA (cluster of 2)
#define LOG2E 1.4426950408889634f
#define LN2   0.6931471805599453f

// ---------------- device scratch ---------------------------------------------
__device__ float g_lseRow[S];
__device__ float g_mT[S];
__device__ float g_lseObs[S];
__device__ float g_Cfold[S];                 // mT - lseObs
__device__ float g_initAdd[S];               // log_softmax(prior) - lseObs
__device__ __nv_bfloat16 g_expT2[2 * S * JH];  // [rank][i][256]

// ---------------- helpers -----------------------------------------------------
__device__ __forceinline__ float ex2_fast(float x) {   // MUFU.EX2
    float r;
    asm("ex2.approx.ftz.f32 %0, %1;" : "=f"(r) : "f"(x));
    return r;
}
__device__ __forceinline__ __nv_bfloat162 u2bf2(unsigned u) {
    __nv_bfloat162 r; *reinterpret_cast<unsigned*>(&r) = u; return r;
}
__device__ __forceinline__ uint32_t smem_u32(const void* p) {
    uint32_t a;
    asm("{ .reg .u64 t; cvta.to.shared.u64 t, %1; cvt.u32.u64 %0, t; }"
        : "=r"(a) : "l"(p));
    return a;
}
__device__ __forceinline__ uint32_t mapa_u32(uint32_t a, uint32_t rank) {
    uint32_t d;
    asm("mapa.shared::cluster.u32 %0, %1, %2;" : "=r"(d) : "r"(a), "r"(rank));
    return d;
}
__device__ __forceinline__ void st_cluster_f32(uint32_t a, float v) {
    asm volatile("st.shared::cluster.f32 [%0], %1;" :: "r"(a), "f"(v) : "memory");
}
__device__ __forceinline__ void mbar_init(uint32_t a, unsigned cnt) {
    asm volatile("mbarrier.init.shared.b64 [%0], %1;" :: "r"(a), "r"(cnt) : "memory");
}
__device__ __forceinline__ void mbar_arrive_cluster(uint32_t a) {
    asm volatile("mbarrier.arrive.release.cluster.shared::cluster.b64 _, [%0];"
                 :: "r"(a) : "memory");
}
__device__ __forceinline__ void mbar_wait_cluster(uint32_t a, unsigned parity) {
    unsigned done;
    asm volatile(
        "{\n\t.reg .pred p;\n\t"
        "mbarrier.try_wait.parity.acquire.cluster.shared::cta.b64 p, [%1], %2;\n\t"
        "selp.b32 %0, 1, 0, p;\n\t}"
        : "=r"(done) : "r"(a), "r"(parity) : "memory");
    if (!done) {
        asm volatile(
            "{\n\t.reg .pred P1;\n\t"
            "WAIT_LOOP_%=:\n\t"
            "mbarrier.try_wait.parity.acquire.cluster.shared::cta.b64 P1, [%0], %1, 0x989680;\n\t"
            "@P1 bra.uni WAIT_DONE_%=;\n\t"
            "bra.uni WAIT_LOOP_%=;\n\t"
            "WAIT_DONE_%=:\n\t}"
            :: "r"(a), "r"(parity) : "memory");
    }
}
#define BAR0() asm volatile("bar.sync 0;" ::: "memory")
#define CLUSTER_SYNC() do { \
    asm volatile("barrier.cluster.arrive.aligned;" ::: "memory"); \
    asm volatile("barrier.cluster.wait.aligned;"   ::: "memory"); \
} while (0)

template <int NW>
__device__ __forceinline__ float blkMax(float v, float* red) {
    #pragma unroll
    for (int o = 16; o > 0; o >>= 1) v = fmaxf(v, __shfl_xor_sync(0xffffffffu, v, o));
    int w = threadIdx.x >> 5;
    if ((threadIdx.x & 31) == 0) red[w] = v;
    __syncthreads();
    float m = red[0];
    #pragma unroll
    for (int k = 1; k < NW; ++k) m = fmaxf(m, red[k]);
    __syncthreads();
    return m;
}
template <int NW>
__device__ __forceinline__ float blkSum(float v, float* red) {
    #pragma unroll
    for (int o = 16; o > 0; o >>= 1) v += __shfl_xor_sync(0xffffffffu, v, o);
    int w = threadIdx.x >> 5;
    if ((threadIdx.x & 31) == 0) red[w] = v;
    __syncthreads();
    float m = 0.f;
    #pragma unroll
    for (int k = 0; k < NW; ++k) m += red[k];
    __syncthreads();
    return m;
}

// ---------------- precompute kernels (256 threads each) ------------------------
__global__ void k_rowlse(const float* __restrict__ ST) {
    __shared__ float red[8];
    int i = blockIdx.x, t = threadIdx.x;
    float x0 = ST[i * S + t], x1 = ST[i * S + t + 256];
    float M = blkMax<8>(fmaxf(x0, x1), red);
    float Ssum = blkSum<8>(expf(x0 - M) + expf(x1 - M), red);
    if (t == 0) g_lseRow[i] = M + logf(Ssum);
}
__global__ void k_colmax(const float* __restrict__ ST) {
    int j = blockIdx.x * blockDim.x + threadIdx.x;
    float m = -1e30f;
    for (int i = 0; i < S; ++i) m = fmaxf(m, ST[i * S + j] - g_lseRow[i]);
    g_mT[j] = m;
}
__global__ void k_expT(const float* __restrict__ ST) {
    int i = blockIdx.x;
    float l = g_lseRow[i];
    for (int j = threadIdx.x; j < S; j += 256) {
        float v = expf(ST[i * S + j] - l - g_mT[j]);
        int rank = j >> 8, c = j & 255;
        g_expT2[((size_t)rank * S + i) * JH + c] = __float2bfloat16(v);
    }
}
__global__ void k_obslse(const float* __restrict__ OT) {
    __shared__ float red[8];
    int s = blockIdx.x, t = threadIdx.x;
    const float* row = OT + (size_t)s * OBS_N;
    float m = -1e30f;
    for (int k = t; k < OBS_N; k += 256) m = fmaxf(m, row[k]);
    float M = blkMax<8>(m, red);
    float acc = 0.f;
    for (int k = t; k < OBS_N; k += 256) acc += expf(row[k] - M);
    float Ssum = blkSum<8>(acc, red);
    if (t == 0) {
        float lse = M + logf(Ssum);
        g_lseObs[s] = lse;
        g_Cfold[s]  = g_mT[s] - lse;
    }
}
__global__ void k_prior(const float* __restrict__ prior) {
    __shared__ float red[16];
    int t = threadIdx.x;
    float p = prior[t];
    float M = blkMax<16>(p, red);
    float Ssum = blkSum<16>(expf(p - M), red);
    float lse = M + logf(Ssum);
    g_initAdd[t] = (p - lse) - g_lseObs[t];
}

// ---------------- forward kernel ------------------------------------------------
// 512 threads, cluster of 2 (j-split). Warp specialization:
//   warps 0-7  : own-half matvec (256 i-rows; sA_own warp-local) + reduce + epilogue
//   warps 8-15 : wait exchange -> write sA_peer (warp-local) -> peer-half matvec
// One bar.sync 0 per step. sP double-buffered by step parity.
// Warp w rows: 16 SMEM (sT rows w*16..+16) + 16 reg (eReg). 16-row bf16x2 chunks.
//
// SMEM (bytes):
//  [0,131072)        sT    bf16 [256][256]
//  [131072,163840)   sP    f32 [2][16][256] (double buffer)
//  [163840,165888)   sA    bf16x2 [512] (RAW alpha, replicated halves)
//  [165888,166912)   sCf   f32 [256]
//  [166912,169088)   sRecv f32 [2][272] ([0..255]=raw, [256..263]=warp maxes)
//  [169088,173184)   sOb   int [1024]
//  [173184,173248)   sRed  f32 [16]
//  [173248,173264)   mbar  2 x u64
#define OFF_P    131072
#define OFF_A    163840
#define OFF_CF   165888
#define OFF_RECV 166912
#define OFF_OB   169088
#define OFF_RED  173184
#define OFF_MB   173248
#define SMEM_TOTAL 173312
#define RSTRIDE 272

__global__ void __launch_bounds__(NTHREADS, 1) __cluster_dims__(2, 1, 1)
k_forward(const int* __restrict__ obs, const float* __restrict__ OT,
          float* __restrict__ out) {
    extern __shared__ char smem[];
    __nv_bfloat16*  sT   = reinterpret_cast<__nv_bfloat16*>(smem);
    float*          sP   = reinterpret_cast<float*>(smem + OFF_P);
    __nv_bfloat162* sA   = reinterpret_cast<__nv_bfloat162*>(smem + OFF_A);
    float*          sCf  = reinterpret_cast<float*>(smem + OFF_CF);
    float*          sRecv= reinterpret_cast<float*>(smem + OFF_RECV);
    int*            sOb  = reinterpret_cast<int*>(smem + OFF_OB);
    float*          sRed = reinterpret_cast<float*>(smem + OFF_RED);

    const int t    = threadIdx.x;
    const int rank = blockIdx.x & 1;
    const int b    = blockIdx.x >> 1;
    const int wid  = t >> 5, oct = t & 31;

    const __nv_bfloat16* gT = g_expT2 + (size_t)rank * S * JH;

    const uint32_t mbLoc    = smem_u32(smem + OFF_MB);
    const uint32_t mbPeer   = mapa_u32(mbLoc, (uint32_t)(rank ^ 1));
    const uint32_t recvPeer = mapa_u32(smem_u32(sRecv), (uint32_t)(rank ^ 1));

    if (t == 0) { mbar_init(mbLoc, 256); mbar_init(mbLoc + 8, 256); }

    const int ownBase  = rank * JH;
    const int peerBase = (rank ^ 1) * JH;

    // one-time SMEM copy: sT row w*16+k <- abs half row
    //   w<8 : ownBase  + w*32 + k       (k<16)
    //   w>=8: peerBase + (w-8)*32 + k
    {
        const uint4* src = reinterpret_cast<const uint4*>(gT);   // 32 uint4/row
        uint4* dst = reinterpret_cast<uint4*>(sT);
        for (int idx = t; idx < 256 * 32; idx += NTHREADS) {
            int r = idx >> 5, c = idx & 31;
            int w = r >> 4, k = r & 15;
            int iabs = (w < 8) ? (ownBase + w * 32 + k)
                               : (peerBase + (w - 8) * 32 + k);
            dst[idx] = src[iabs * 32 + c];
        }
    }
    for (int k = t; k < JH; k += NTHREADS)   sCf[k] = g_Cfold[ownBase + k];
    for (int k = t; k < TLEN; k += NTHREADS) sOb[k] = obs[b * TLEN + k];

    // register rows (step-invariant): warp's rows 16..31 of its half
    uint4 eReg[16];
    {
        const int rb = (wid < 8) ? (ownBase + wid * 32 + 16)
                                 : (peerBase + (wid - 8) * 32 + 16);
        #pragma unroll
        for (int m = 0; m < 16; ++m)
            eReg[m] = __ldg(reinterpret_cast<const uint4*>(
                gT + (size_t)(rb + m) * JH + oct * 8));
    }
    __syncthreads();

    // ---- init: alpha0 raw (log2-offset), ship exchange 0 ----
    float E2;
    float rawOwn = 0.f;
    {
        int o0 = sOb[0];
        int jj = (t < 256) ? t : 255;         // clamped for inactive threads
        float aO = -1e30f, aP = -1e30f;
        if (t < 256) {
            aO = __ldg(OT + (size_t)(ownBase + jj) * OBS_N + o0) + g_initAdd[ownBase + jj];
            aP = __ldg(OT + (size_t)(peerBase + jj) * OBS_N + o0) + g_initAdd[peerBase + jj];
        }
        float M = blkMax<16>(fmaxf(aO, aP), sRed);
        E2 = M * LOG2E;
        if (t < 256) {
            rawOwn = ex2_fast((aO - M) * LOG2E);
            sA[ownBase + t] = __bfloat162bfloat162(__float2bfloat16(rawOwn));
            st_cluster_f32(recvPeer + (unsigned)t * 4u, rawOwn);
            float m = rawOwn;
            #pragma unroll
            for (int o = 16; o > 0; o >>= 1)
                m = fmaxf(m, __shfl_xor_sync(0xffffffffu, m, o));
            if (oct == 0) {
                st_cluster_f32(recvPeer + (unsigned)(256 + wid) * 4u, m);
                sRed[wid] = m;
            }
        }
    }
    CLUSTER_SYNC();                         // peer mbar inits + init stores visible
    if (t < 256) mbar_arrive_cluster(mbPeer);   // exchange 0, slot 0
    __syncthreads();

    const float cf   = sCf[(t < 256) ? t : 0];
    const float* wPtr = OT + (size_t)(ownBase + ((t < 256) ? t : 0)) * OBS_N;
    const __nv_bfloat162 z = __float2bfloat162_rn(0.f);
    const int sTbase = wid * 16;

    int slot = 0;
    int ph0 = 0, ph1 = 0;
    float scl = 1.f;

    #pragma unroll 1
    for (int step = 1; step <= TLEN; ++step) {
        const int pbuf = (step & 1) * 4096;     // sP double buffer (floats)
        float facc[8];
        #pragma unroll
        for (int k = 0; k < 8; ++k) facc[k] = 0.f;

        if (wid < 8) {
            // ======== producer group: own-half matvec + reduce + epilogue ====
            const int ot = (step < TLEN) ? sOb[step] : 0;
            const float w = __ldg(wPtr + ot);
            const int aB = ownBase + wid * 32;

            // chunk 0: 16 SMEM rows
            {
                __nv_bfloat162 ac0 = z, ac1 = z, ac2 = z, ac3 = z;
                #pragma unroll
                for (int u = 0; u < 4; ++u) {
                    uint4 av = *reinterpret_cast<const uint4*>(sA + aB + u * 4);
                    unsigned avv[4] = {av.x, av.y, av.z, av.w};
                    #pragma unroll
                    for (int r = 0; r < 4; ++r) {
                        uint4 e = *reinterpret_cast<const uint4*>(
                            sT + (size_t)(sTbase + u * 4 + r) * JH + oct * 8);
                        __nv_bfloat162 a = u2bf2(avv[r]);
                        ac0 = __hfma2(a, u2bf2(e.x), ac0);
                        ac1 = __hfma2(a, u2bf2(e.y), ac1);
                        ac2 = __hfma2(a, u2bf2(e.z), ac2);
                        ac3 = __hfma2(a, u2bf2(e.w), ac3);
                    }
                }
                facc[0] += __low2float(ac0); facc[1] += __high2float(ac0);
                facc[2] += __low2float(ac1); facc[3] += __high2float(ac1);
                facc[4] += __low2float(ac2); facc[5] += __high2float(ac2);
                facc[6] += __low2float(ac3); facc[7] += __high2float(ac3);
            }
            // chunk 1: 16 reg rows
            {
                __nv_bfloat162 ac0 = z, ac1 = z, ac2 = z, ac3 = z;
                #pragma unroll
                for (int u = 0; u < 4; ++u) {
                    uint4 av = *reinterpret_cast<const uint4*>(sA + aB + 16 + u * 4);
                    unsigned avv[4] = {av.x, av.y, av.z, av.w};
                    #pragma unroll
                    for (int r = 0; r < 4; ++r) {
                        uint4 e = eReg[u * 4 + r];
                        __nv_bfloat162 a = u2bf2(avv[r]);
                        ac0 = __hfma2(a, u2bf2(e.x), ac0);
                        ac1 = __hfma2(a, u2bf2(e.y), ac1);
                        ac2 = __hfma2(a, u2bf2(e.z), ac2);
                        ac3 = __hfma2(a, u2bf2(e.w), ac3);
                    }
                }
                facc[0] += __low2float(ac0); facc[1] += __high2float(ac0);
                facc[2] += __low2float(ac1); facc[3] += __high2float(ac1);
                facc[4] += __low2float(ac2); facc[5] += __high2float(ac2);
                facc[6] += __low2float(ac3); facc[7] += __high2float(ac3);
            }
            // store partials
            {
                float4* ps = reinterpret_cast<float4*>(sP + pbuf + wid * 256 + oct * 8);
                ps[0] = make_float4(facc[0], facc[1], facc[2], facc[3]);
                ps[1] = make_float4(facc[4], facc[5], facc[6], facc[7]);
            }
            BAR0();                                   // all 16 sP rows ready
            float p = 0.f;
            #pragma unroll
            for (int q = 0; q < 16; ++q) p += sP[pbuf + q * 256 + t];

            // exchange(step-1): maxes for renorm scale
            mbar_wait_cluster(mbLoc + slot * 8, (unsigned)(slot ? ph1 : ph0));
            if (slot) ph1 ^= 1; else ph0 ^= 1;
            {
                const unsigned rbase = (unsigned)(slot * RSTRIDE);
                float M2 = 1e-30f;
                #pragma unroll
                for (int k = 0; k < 8; ++k) M2 = fmaxf(M2, sRed[k]);
                #pragma unroll
                for (int k = 0; k < 8; ++k) M2 = fmaxf(M2, sRecv[rbase + 256 + k]);
                int m2 = (__float_as_int(M2) >> 23) - 127;
                scl = __int_as_float((127 - m2) << 23);     // 2^-m2, exact
                E2 += (float)m2;
            }
            // epilogue
            float raw = p * ex2_fast((w + cf) * LOG2E) * scl;
            const int sendSlot = slot ^ 1;
            const unsigned sbase = (unsigned)(sendSlot * RSTRIDE);
            st_cluster_f32(recvPeer + (sbase + t) * 4u, raw);
            float m = raw;
            #pragma unroll
            for (int o = 16; o > 0; o >>= 1)
                m = fmaxf(m, __shfl_xor_sync(0xffffffffu, m, o));
            if (oct == 0) {
                st_cluster_f32(recvPeer + (sbase + 256 + wid) * 4u, m);
                sRed[wid] = m;
            }
            mbar_arrive_cluster(mbPeer + sendSlot * 8);
            sA[ownBase + t] = __bfloat162bfloat162(__float2bfloat16(raw));
            __syncwarp();
            rawOwn = raw;
        } else {
            // ======== consumer group: wait, sA_peer, peer-half matvec ========
            mbar_wait_cluster(mbLoc + slot * 8, (unsigned)(slot ? ph1 : ph0));
            if (slot) ph1 ^= 1; else ph0 ^= 1;
            const int jp = t - 256;
            sA[peerBase + jp] = __bfloat162bfloat162(
                __float2bfloat16(sRecv[slot * RSTRIDE + jp]));
            __syncwarp();     // warp-local: this warp reads exactly its lanes' rows
            const int aB = peerBase + (wid - 8) * 32;

            {
                __nv_bfloat162 ac0 = z, ac1 = z, ac2 = z, ac3 = z;
                #pragma unroll
                for (int u = 0; u < 4; ++u) {
                    uint4 av = *reinterpret_cast<const uint4*>(sA + aB + u * 4);
                    unsigned avv[4] = {av.x, av.y, av.z, av.w};
                    #pragma unroll
                    for (int r = 0; r < 4; ++r) {
                        uint4 e = *reinterpret_cast<const uint4*>(
                            sT + (size_t)(sTbase + u * 4 + r) * JH + oct * 8);
                        __nv_bfloat162 a = u2bf2(avv[r]);
                        ac0 = __hfma2(a, u2bf2(e.x), ac0);
                        ac1 = __hfma2(a, u2bf2(e.y), ac1);
                        ac2 = __hfma2(a, u2bf2(e.z), ac2);
                        ac3 = __hfma2(a, u2bf2(e.w), ac3);
                    }
                }
                facc[0] += __low2float(ac0); facc[1] += __high2float(ac0);
                facc[2] += __low2float(ac1); facc[3] += __high2float(ac1);
                facc[4] += __low2float(ac2); facc[5] += __high2float(ac2);
                facc[6] += __low2float(ac3); facc[7] += __high2float(ac3);
            }
            {
                __nv_bfloat162 ac0 = z, ac1 = z, ac2 = z, ac3 = z;
                #pragma unroll
                for (int u = 0; u < 4; ++u) {
                    uint4 av = *reinterpret_cast<const uint4*>(sA + aB + 16 + u * 4);
                    unsigned avv[4] = {av.x, av.y, av.z, av.w};
                    #pragma unroll
                    for (int r = 0; r < 4; ++r) {
                        uint4 e = eReg[u * 4 + r];
                        __nv_bfloat162 a = u2bf2(avv[r]);
                        ac0 = __hfma2(a, u2bf2(e.x), ac0);
                        ac1 = __hfma2(a, u2bf2(e.y), ac1);
                        ac2 = __hfma2(a, u2bf2(e.z), ac2);
                        ac3 = __hfma2(a, u2bf2(e.w), ac3);
                    }
                }
                facc[0] += __low2float(ac0); facc[1] += __high2float(ac0);
                facc[2] += __low2float(ac1); facc[3] += __high2float(ac1);
                facc[4] += __low2float(ac2); facc[5] += __high2float(ac2);
                facc[6] += __low2float(ac3); facc[7] += __high2float(ac3);
            }
            {
                float4* ps = reinterpret_cast<float4*>(sP + pbuf + wid * 256 + oct * 8);
                ps[0] = make_float4(facc[0], facc[1], facc[2], facc[3]);
                ps[1] = make_float4(facc[4], facc[5], facc[6], facc[7]);
            }
            BAR0();
        }
        slot ^= 1;
    }

    // ---- final: own raw + peer raw (pending exchange TLEN) ----
    if (wid < 8) {
        mbar_wait_cluster(mbLoc + slot * 8, (unsigned)(slot ? ph1 : ph0));
        float v = rawOwn + sRecv[slot * RSTRIDE + t];
        #pragma unroll
        for (int o = 16; o > 0; o >>= 1) v += __shfl_xor_sync(0xffffffffu, v, o);
        if (oct == 0) sRed[wid] = v;
    }
    BAR0();
    if (rank == 0 && t == 0) {
        float total = 0.f;
        #pragma unroll
        for (int k = 0; k < 8; ++k) total += sRed[k];
        out[b] = logf(total) + E2 * LN2;
    }
    CLUSTER_SYNC();
}

// ---------------- launch -------------------------------------------------------
extern "C" void kernel_launch(void* const* d_in, const int* in_sizes, int n_in,
                              void* d_out, int out_size) {
    const int*   obs   = (const int*)d_in[0];
    const float* ST    = (const float*)d_in[1];
    const float* OT    = (const float*)d_in[2];
    const float* prior = (const float*)d_in[3];
    float* out = (float*)d_out;

    cudaFuncSetAttribute(k_forward, cudaFuncAttributeMaxDynamicSharedMemorySize,
                         SMEM_TOTAL);

    k_rowlse<<<S, 256>>>(ST);
    k_colmax<<<4, 128>>>(ST);
    k_expT<<<S, 256>>>(ST);
    k_obslse<<<S, 256>>>(OT);
    k_prior<<<1, S>>>(prior);
    k_forward<<<BATCH * 2, NTHREADS, SMEM_TOTAL>>>(obs, OT, out);
}